// round 7
// baseline (speedup 1.0000x reference)
#include <cuda_runtime.h>
#include <cstdint>

#define SEQ    2048
#define BATCH  4096
#define IN     4
#define HID    3
#define UNR    8                  // timesteps per pipeline stage
#define STAGES 4                  // smem pipeline depth (32 KB)
#define NGRP   (SEQ / UNR)        // 256 groups
#define NPAIR  (BATCH / 2)        // 2048 chain pairs

// ---- cp.async ----
__device__ __forceinline__ void cp_async16(void* smem_dst, const void* gmem_src) {
    uint32_t s;
    asm("{ .reg .u64 t; cvta.to.shared.u64 t, %1; cvt.u32.u64 %0, t; }"
        : "=r"(s) : "l"(smem_dst));
    asm volatile("cp.async.ca.shared.global [%0], [%1], 16;"
                 :: "r"(s), "l"(gmem_src) : "memory");
}
__device__ __forceinline__ void cp_async_commit() {
    asm volatile("cp.async.commit_group;" ::: "memory");
}
template <int N>
__device__ __forceinline__ void cp_async_wait() {
    asm volatile("cp.async.wait_group %0;" :: "n"(N) : "memory");
}

__global__ void __launch_bounds__(32, 1)
rnn_relu_kernel(const float* __restrict__ x,      // [SEQ, BATCH, 4]
                const float* __restrict__ h0,     // [1, BATCH, 3]
                const float* __restrict__ W_ih,   // [3, 4]
                const float* __restrict__ W_hh,   // [3, 3]
                const float* __restrict__ b_ih,   // [3]
                const float* __restrict__ b_hh,   // [3]
                float* __restrict__ out)
{
    // One warp per block; each thread owns TWO adjacent batch chains (2p, 2p+1).
    __shared__ float4 xs[STAGES][UNR][32][2];   // 32 KB

    const int lane = threadIdx.x;
    const int p  = blockIdx.x * 32 + lane;   // pair index 0..NPAIR-1
    const int bA = 2 * p;                    // chain A batch; chain B = bA+1

    // Uniform weights/biases in registers.
    float wih[HID][IN];
    float whh[HID][HID];
    float bias[HID];
#pragma unroll
    for (int j = 0; j < HID; j++) {
#pragma unroll
        for (int i = 0; i < IN; i++) wih[j][i] = W_ih[j * IN + i];
#pragma unroll
        for (int i = 0; i < HID; i++) whh[j][i] = W_hh[j * HID + i];
        bias[j] = b_ih[j] + b_hh[j];
    }

    float hA0 = h0[bA * HID + 0], hA1 = h0[bA * HID + 1], hA2 = h0[bA * HID + 2];
    float hB0 = h0[bA * HID + 3], hB1 = h0[bA * HID + 4], hB2 = h0[bA * HID + 5];

    const float4* __restrict__ xv = (const float4*)x;  // [SEQ][BATCH]
    float* __restrict__ outs  = out;
    float* __restrict__ hlast = out + (size_t)SEQ * BATCH * HID;

    // Prime STAGES-1 = 3 stages (24 timesteps of lookahead, both chains).
#pragma unroll
    for (int s = 0; s < STAGES - 1; s++) {
#pragma unroll
        for (int k = 0; k < UNR; k++) {
            const size_t src = (size_t)(s * UNR + k) * BATCH + bA;
            cp_async16(&xs[s][k][lane][0], &xv[src]);
            cp_async16(&xs[s][k][lane][1], &xv[src + 1]);
        }
        cp_async_commit();
    }

    for (int g = 0; g < NGRP; g++) {
        const int stage = g & (STAGES - 1);
        cp_async_wait<STAGES - 2>();   // this stage complete (self-written smem)

        const int t0 = g * UNR;
#pragma unroll
        for (int k = 0; k < UNR; k++) {
            const float4 xa = xs[stage][k][lane][0];
            const float4 xb = xs[stage][k][lane][1];

            // Input projections — both chains, off the serial chains.
            float pA0 = fmaf(wih[0][0], xa.x, bias[0]);
            float pA1 = fmaf(wih[1][0], xa.x, bias[1]);
            float pA2 = fmaf(wih[2][0], xa.x, bias[2]);
            float pB0 = fmaf(wih[0][0], xb.x, bias[0]);
            float pB1 = fmaf(wih[1][0], xb.x, bias[1]);
            float pB2 = fmaf(wih[2][0], xb.x, bias[2]);
            pA0 = fmaf(wih[0][1], xa.y, pA0);
            pA1 = fmaf(wih[1][1], xa.y, pA1);
            pA2 = fmaf(wih[2][1], xa.y, pA2);
            pB0 = fmaf(wih[0][1], xb.y, pB0);
            pB1 = fmaf(wih[1][1], xb.y, pB1);
            pB2 = fmaf(wih[2][1], xb.y, pB2);
            pA0 = fmaf(wih[0][2], xa.z, pA0);
            pA1 = fmaf(wih[1][2], xa.z, pA1);
            pA2 = fmaf(wih[2][2], xa.z, pA2);
            pB0 = fmaf(wih[0][2], xb.z, pB0);
            pB1 = fmaf(wih[1][2], xb.z, pB1);
            pB2 = fmaf(wih[2][2], xb.z, pB2);
            pA0 = fmaf(wih[0][3], xa.w, pA0);
            pA1 = fmaf(wih[1][3], xa.w, pA1);
            pA2 = fmaf(wih[2][3], xa.w, pA2);
            pB0 = fmaf(wih[0][3], xb.w, pB0);
            pB1 = fmaf(wih[1][3], xb.w, pB1);
            pB2 = fmaf(wih[2][3], xb.w, pB2);

            // Recurrent updates — two independent serial chains interleave.
            float aA0 = fmaf(whh[0][0], hA0, pA0);
            float aA1 = fmaf(whh[1][0], hA0, pA1);
            float aA2 = fmaf(whh[2][0], hA0, pA2);
            float aB0 = fmaf(whh[0][0], hB0, pB0);
            float aB1 = fmaf(whh[1][0], hB0, pB1);
            float aB2 = fmaf(whh[2][0], hB0, pB2);
            aA0 = fmaf(whh[0][1], hA1, aA0);
            aA1 = fmaf(whh[1][1], hA1, aA1);
            aA2 = fmaf(whh[2][1], hA1, aA2);
            aB0 = fmaf(whh[0][1], hB1, aB0);
            aB1 = fmaf(whh[1][1], hB1, aB1);
            aB2 = fmaf(whh[2][1], hB1, aB2);
            aA0 = fmaf(whh[0][2], hA2, aA0);
            aA1 = fmaf(whh[1][2], hA2, aA1);
            aA2 = fmaf(whh[2][2], hA2, aA2);
            aB0 = fmaf(whh[0][2], hB2, aB0);
            aB1 = fmaf(whh[1][2], hB2, aB1);
            aB2 = fmaf(whh[2][2], hB2, aB2);

            hA0 = fmaxf(aA0, 0.0f);
            hA1 = fmaxf(aA1, 0.0f);
            hA2 = fmaxf(aA2, 0.0f);
            hB0 = fmaxf(aB0, 0.0f);
            hB1 = fmaxf(aB1, 0.0f);
            hB2 = fmaxf(aB2, 0.0f);

            // 6 contiguous floats (24 B, 8-aligned) -> 3 x STG.64 streaming.
            const size_t o = ((size_t)(t0 + k) * BATCH + bA) * HID;
            __stcs((float2*)(outs + o),     make_float2(hA0, hA1));
            __stcs((float2*)(outs + o + 2), make_float2(hA2, hB0));
            __stcs((float2*)(outs + o + 4), make_float2(hB1, hB2));

            // Refill this (k, stage) slot for group g + STAGES - 1.
            const int gnext = g + STAGES - 1;
            if (gnext < NGRP) {
                const size_t src = (size_t)(gnext * UNR + k) * BATCH + bA;
                const int ns = gnext & (STAGES - 1);
                cp_async16(&xs[ns][k][lane][0], &xv[src]);
                cp_async16(&xs[ns][k][lane][1], &xv[src + 1]);
            }
        }
        cp_async_commit();  // uniform group accounting on the tail
    }

    hlast[bA * HID + 0] = hA0;
    hlast[bA * HID + 1] = hA1;
    hlast[bA * HID + 2] = hA2;
    hlast[bA * HID + 3] = hB0;
    hlast[bA * HID + 4] = hB1;
    hlast[bA * HID + 5] = hB2;
}

extern "C" void kernel_launch(void* const* d_in, const int* in_sizes, int n_in,
                              void* d_out, int out_size)
{
    const float* x    = (const float*)d_in[0];
    const float* h0   = (const float*)d_in[1];
    const float* W_ih = (const float*)d_in[2];
    const float* W_hh = (const float*)d_in[3];
    const float* b_ih = (const float*)d_in[4];
    const float* b_hh = (const float*)d_in[5];
    float* out = (float*)d_out;

    // 2048 chain pairs, one per thread; one warp per block, sync-free.
    rnn_relu_kernel<<<NPAIR / 32, 32>>>(x, h0, W_ih, W_hh, b_ih, b_hh, out);
}

// round 8
// speedup vs baseline: 1.3966x; 1.3966x over previous
#include <cuda_runtime.h>
#include <cstdint>

#define SEQ    2048
#define BATCH  4096
#define IN     4
#define HID    3
#define UNR    16                 // timesteps per pipeline stage/group
#define STAGES 4                  // x smem pipeline depth (32 KB)
#define NGRP   (SEQ / UNR)        // 128 groups

typedef unsigned long long u64;

// ---- packed f32x2 helpers ----
__device__ __forceinline__ u64 pack2(float lo, float hi) {
    u64 r; asm("mov.b64 %0, {%1, %2};" : "=l"(r) : "f"(lo), "f"(hi)); return r;
}
__device__ __forceinline__ u64 bcast2(float v) {
    u64 r; asm("mov.b64 %0, {%1, %1};" : "=l"(r) : "f"(v)); return r;
}
__device__ __forceinline__ u64 fma2(u64 a, u64 b, u64 c) {
    u64 d; asm("fma.rn.f32x2 %0, %1, %2, %3;" : "=l"(d) : "l"(a), "l"(b), "l"(c)); return d;
}
__device__ __forceinline__ float2 unpack2(u64 v) {
    float2 r; asm("mov.b64 {%0, %1}, %2;" : "=f"(r.x), "=f"(r.y) : "l"(v)); return r;
}

// ---- non-bulk cp.async (x input pipeline) ----
__device__ __forceinline__ void cp_async16(void* smem_dst, const void* gmem_src) {
    uint32_t s;
    asm("{ .reg .u64 t; cvta.to.shared.u64 t, %1; cvt.u32.u64 %0, t; }"
        : "=r"(s) : "l"(smem_dst));
    asm volatile("cp.async.ca.shared.global [%0], [%1], 16;"
                 :: "r"(s), "l"(gmem_src) : "memory");
}
__device__ __forceinline__ void cp_async_commit() {
    asm volatile("cp.async.commit_group;" ::: "memory");
}
template <int N>
__device__ __forceinline__ void cp_async_wait() {
    asm volatile("cp.async.wait_group %0;" :: "n"(N) : "memory");
}

// ---- 1D bulk async store smem -> gmem (no tensormap needed) ----
__device__ __forceinline__ uint32_t smem_u32(const void* p) {
    uint32_t s;
    asm("{ .reg .u64 t; cvta.to.shared.u64 t, %1; cvt.u32.u64 %0, t; }"
        : "=r"(s) : "l"(p));
    return s;
}
__device__ __forceinline__ void bulk_store(void* gmem, uint32_t smem_addr, int bytes) {
    asm volatile("cp.async.bulk.global.shared::cta.bulk_group [%0], [%1], %2;"
                 :: "l"(gmem), "r"(smem_addr), "r"(bytes) : "memory");
}
__device__ __forceinline__ void bulk_commit() {
    asm volatile("cp.async.bulk.commit_group;" ::: "memory");
}
template <int N>
__device__ __forceinline__ void bulk_wait() {
    asm volatile("cp.async.bulk.wait_group %0;" :: "n"(N) : "memory");
}
__device__ __forceinline__ void fence_async_shared() {
    asm volatile("fence.proxy.async.shared::cta;" ::: "memory");
}

__global__ void __launch_bounds__(32, 1)
rnn_relu_kernel(const float* __restrict__ x,      // [SEQ, BATCH, 4]
                const float* __restrict__ h0,     // [1, BATCH, 3]
                const float* __restrict__ W_ih,   // [3, 4]
                const float* __restrict__ W_hh,   // [3, 3]
                const float* __restrict__ b_ih,   // [3]
                const float* __restrict__ b_hh,   // [3]
                float* __restrict__ out)
{
    // One warp per block; each thread owns one batch chain and its own smem lane.
    __shared__ float4 xs[STAGES][UNR][32];   // 32 KB input pipeline
    __shared__ float  st[2][UNR][96];        // 12 KB output staging (384 B rows)

    const int lane = threadIdx.x;
    const int b0 = blockIdx.x * 32;
    const int b  = b0 + lane;

    // Weights: projection packed for units (0,1), everything else scalar.
    u64 wih01[IN];
    float wih2[IN];
    float whh[HID][HID];
#pragma unroll
    for (int i = 0; i < IN; i++) {
        wih01[i] = pack2(W_ih[0 * IN + i], W_ih[1 * IN + i]);
        wih2[i]  = W_ih[2 * IN + i];
    }
#pragma unroll
    for (int j = 0; j < HID; j++)
#pragma unroll
        for (int i = 0; i < HID; i++) whh[j][i] = W_hh[j * HID + i];
    const u64   bias01 = pack2(b_ih[0] + b_hh[0], b_ih[1] + b_hh[1]);
    const float bias2  = b_ih[2] + b_hh[2];

    float ha = h0[b * HID + 0];
    float hb = h0[b * HID + 1];
    float hc = h0[b * HID + 2];

    const float4* __restrict__ xv = (const float4*)x;  // [SEQ][BATCH]
    float* __restrict__ outs  = out;
    float* __restrict__ hlast = out + (size_t)SEQ * BATCH * HID;

    // Prime input pipeline: 3 stages = 48 timesteps of lookahead.
#pragma unroll
    for (int s = 0; s < STAGES - 1; s++) {
#pragma unroll
        for (int k = 0; k < UNR; k++)
            cp_async16(&xs[s][k][lane], &xv[(size_t)(s * UNR + k) * BATCH + b]);
        cp_async_commit();
    }

    for (int g = 0; g < NGRP; g++) {
        const int stage = g & (STAGES - 1);
        const int buf   = g & 1;

        // Buffer st[buf] was consumed by the bulk store of group g-2:
        // allow at most 1 outstanding bulk group (g-1's) before refilling.
        if (lane == 0) bulk_wait<1>();
        __syncwarp();                 // lanes wait for lane0's drain

        cp_async_wait<STAGES - 2>();  // this x stage complete (self-written)

        const int t0 = g * UNR;
#pragma unroll
        for (int k = 0; k < UNR; k++) {
            const float4 xt = xs[stage][k][lane];

            // Projection: units (0,1) packed f32x2, unit 2 scalar. Off-chain.
            u64 p01 = fma2(wih01[0], bcast2(xt.x), bias01);
            p01 = fma2(wih01[1], bcast2(xt.y), p01);
            p01 = fma2(wih01[2], bcast2(xt.z), p01);
            p01 = fma2(wih01[3], bcast2(xt.w), p01);
            float p2 = fmaf(wih2[0], xt.x, bias2);
            p2 = fmaf(wih2[1], xt.y, p2);
            p2 = fmaf(wih2[2], xt.z, p2);
            p2 = fmaf(wih2[3], xt.w, p2);
            const float2 p = unpack2(p01);

            // Scalar recurrence: serial chain = 3 FFMA + max ≈ 16 cyc.
            float a0 = fmaf(whh[0][0], ha, p.x);
            float a1 = fmaf(whh[1][0], ha, p.y);
            float a2 = fmaf(whh[2][0], ha, p2);
            a0 = fmaf(whh[0][1], hb, a0);
            a1 = fmaf(whh[1][1], hb, a1);
            a2 = fmaf(whh[2][1], hb, a2);
            a0 = fmaf(whh[0][2], hc, a0);
            a1 = fmaf(whh[1][2], hc, a1);
            a2 = fmaf(whh[2][2], hc, a2);

            ha = fmaxf(a0, 0.0f);
            hb = fmaxf(a1, 0.0f);
            hc = fmaxf(a2, 0.0f);

            // Stage outputs in smem (conflict-free: lane*3 mod 32 distinct).
            st[buf][k][lane * 3 + 0] = ha;
            st[buf][k][lane * 3 + 1] = hb;
            st[buf][k][lane * 3 + 2] = hc;
        }

        // Refill this x stage for group g + STAGES - 1.
        const int gnext = g + STAGES - 1;
        if (gnext < NGRP) {
            const int ns = gnext & (STAGES - 1);
#pragma unroll
            for (int k = 0; k < UNR; k++)
                cp_async16(&xs[ns][k][lane],
                           &xv[(size_t)(gnext * UNR + k) * BATCH + b]);
        }
        cp_async_commit();

        // Drain st[buf] to gmem via 1D bulk async stores (16 rows x 384 B).
        __syncwarp();                 // all lanes' STS visible
        if (lane == 0) {
            fence_async_shared();     // generic->async proxy ordering
#pragma unroll
            for (int k = 0; k < UNR; k++)
                bulk_store(outs + ((size_t)(t0 + k) * BATCH + b0) * HID,
                           smem_u32(&st[buf][k][0]), 96 * 4);
            bulk_commit();
        }
    }

    // All bulk stores must complete before we finish.
    if (lane == 0) bulk_wait<0>();
    __syncwarp();

    hlast[b * HID + 0] = ha;
    hlast[b * HID + 1] = hb;
    hlast[b * HID + 2] = hc;
}

extern "C" void kernel_launch(void* const* d_in, const int* in_sizes, int n_in,
                              void* d_out, int out_size)
{
    const float* x    = (const float*)d_in[0];
    const float* h0   = (const float*)d_in[1];
    const float* W_ih = (const float*)d_in[2];
    const float* W_hh = (const float*)d_in[3];
    const float* b_ih = (const float*)d_in[4];
    const float* b_hh = (const float*)d_in[5];
    float* out = (float*)d_out;

    rnn_relu_kernel<<<BATCH / 32, 32>>>(x, h0, W_ih, W_hh, b_ih, b_hh, out);
}

// round 10
// speedup vs baseline: 1.7462x; 1.2503x over previous
#include <cuda_runtime.h>
#include <cstdint>

#define SEQ    2048
#define BATCH  4096
#define IN     4
#define HID    3
#define UNR    16                 // timesteps per group
#define XS     4                  // producer x smem pipeline depth
#define RS     4                  // p-ring slots
#define NGRP   (SEQ / UNR)        // 128 groups

// ---- cp.async (producer x pipeline) ----
__device__ __forceinline__ void cp_async16(void* smem_dst, const void* gmem_src) {
    uint32_t s;
    asm("{ .reg .u64 t; cvta.to.shared.u64 t, %1; cvt.u32.u64 %0, t; }"
        : "=r"(s) : "l"(smem_dst));
    asm volatile("cp.async.ca.shared.global [%0], [%1], 16;"
                 :: "r"(s), "l"(gmem_src) : "memory");
}
__device__ __forceinline__ void cp_async_commit() {
    asm volatile("cp.async.commit_group;" ::: "memory");
}
template <int N>
__device__ __forceinline__ void cp_async_wait() {
    asm volatile("cp.async.wait_group %0;" :: "n"(N) : "memory");
}

// ---- mbarrier ----
__device__ __forceinline__ uint32_t smem_u32(const void* p) {
    uint32_t s;
    asm("{ .reg .u64 t; cvta.to.shared.u64 t, %1; cvt.u32.u64 %0, t; }"
        : "=r"(s) : "l"(p));
    return s;
}
__device__ __forceinline__ void mbar_init(uint32_t a, uint32_t cnt) {
    asm volatile("mbarrier.init.shared.b64 [%0], %1;" :: "r"(a), "r"(cnt) : "memory");
}
__device__ __forceinline__ void mbar_arrive(uint32_t a) {
    asm volatile("mbarrier.arrive.shared.b64 _, [%0];" :: "r"(a) : "memory");
}
__device__ __forceinline__ void mbar_wait(uint32_t a, uint32_t parity) {
    uint32_t done;
    asm volatile(
        "{\n\t.reg .pred p;\n\t"
        "mbarrier.try_wait.parity.acquire.cta.shared::cta.b64 p, [%1], %2;\n\t"
        "selp.b32 %0, 1, 0, p;\n\t}"
        : "=r"(done) : "r"(a), "r"(parity) : "memory");
    if (!done) {
        asm volatile(
            "{\n\t.reg .pred P1;\n\t"
            "W_%=:\n\t"
            "mbarrier.try_wait.parity.acquire.cta.shared::cta.b64 P1, [%0], %1, 0x989680;\n\t"
            "@P1 bra.uni D_%=;\n\t"
            "bra.uni W_%=;\n\t"
            "D_%=:\n\t}"
            :: "r"(a), "r"(parity) : "memory");
    }
}

__global__ void __launch_bounds__(64, 1)
rnn_relu_kernel(const float* __restrict__ x,      // [SEQ, BATCH, 4]
                const float* __restrict__ h0,     // [1, BATCH, 3]
                const float* __restrict__ W_ih,   // [3, 4]
                const float* __restrict__ W_hh,   // [3, 3]
                const float* __restrict__ b_ih,   // [3]
                const float* __restrict__ b_hh,   // [3]
                float* __restrict__ out)
{
    // Warp 0: consumer (recurrence + store). Warp 1: producer (x load + projection).
    __shared__ float4 xs[XS][UNR][32];   // 32 KB producer x pipeline
    __shared__ float4 pr[RS][UNR][32];   // 32 KB projection ring
    __shared__ unsigned long long mb_full[RS], mb_empty[RS];

    const int lane = threadIdx.x & 31;
    const int warp = threadIdx.x >> 5;
    const int b = blockIdx.x * 32 + lane;

    if (threadIdx.x == 0) {
#pragma unroll
        for (int s = 0; s < RS; s++) {
            mbar_init(smem_u32(&mb_full[s]), 32);
            mbar_init(smem_u32(&mb_empty[s]), 32);
        }
    }
    __syncthreads();   // once, before any STS is in flight — cheap

    const float4* __restrict__ xv = (const float4*)x;  // [SEQ][BATCH]

    if (warp == 1) {
        // ================= producer: x load + input projection =================
        float wih[HID][IN];
        float bias[HID];
#pragma unroll
        for (int j = 0; j < HID; j++) {
#pragma unroll
            for (int i = 0; i < IN; i++) wih[j][i] = W_ih[j * IN + i];
            bias[j] = b_ih[j] + b_hh[j];
        }

        // Prime x pipeline: groups 0..2 into stages 0..2 (48 timesteps lookahead).
#pragma unroll
        for (int s = 0; s < XS - 1; s++) {
#pragma unroll
            for (int k = 0; k < UNR; k++)
                cp_async16(&xs[s][k][lane], &xv[(size_t)(s * UNR + k) * BATCH + b]);
            cp_async_commit();
        }

        uint32_t pph = 1;   // fresh-barrier parity trick: first empty-wait passes
        for (int g = 0; g < NGRP; g++) {
            const int slot = g & (RS - 1);        // p-ring slot AND x stage (group g)

            cp_async_wait<XS - 2>();                      // xs for group g complete
            mbar_wait(smem_u32(&mb_empty[slot]), pph);    // ring slot free

#pragma unroll
            for (int k = 0; k < UNR; k++) {
                const float4 xt = xs[slot][k][lane];
                float p0 = fmaf(wih[0][0], xt.x, bias[0]);
                float p1 = fmaf(wih[1][0], xt.x, bias[1]);
                float p2 = fmaf(wih[2][0], xt.x, bias[2]);
                p0 = fmaf(wih[0][1], xt.y, p0);
                p1 = fmaf(wih[1][1], xt.y, p1);
                p2 = fmaf(wih[2][1], xt.y, p2);
                p0 = fmaf(wih[0][2], xt.z, p0);
                p1 = fmaf(wih[1][2], xt.z, p1);
                p2 = fmaf(wih[2][2], xt.z, p2);
                p0 = fmaf(wih[0][3], xt.w, p0);
                p1 = fmaf(wih[1][3], xt.w, p1);
                p2 = fmaf(wih[2][3], xt.w, p2);
                pr[slot][k][lane] = make_float4(p0, p1, p2, 0.0f);
            }
            mbar_arrive(smem_u32(&mb_full[slot]));  // release: STS above visible

            // Refill stage for group g+XS-1 — FIXED: stage (g+XS-1)&(XS-1),
            // so group n always lives in stage n&(XS-1). (R9 bug: used `slot`.)
            const int gnext = g + XS - 1;
            if (gnext < NGRP) {
                const int ns = gnext & (XS - 1);
#pragma unroll
                for (int k = 0; k < UNR; k++)
                    cp_async16(&xs[ns][k][lane],
                               &xv[(size_t)(gnext * UNR + k) * BATCH + b]);
            }
            cp_async_commit();

            if (slot == RS - 1) pph ^= 1;
        }

    } else {
        // ================= consumer: recurrence + store =================
        float whh[HID][HID];
#pragma unroll
        for (int j = 0; j < HID; j++)
#pragma unroll
            for (int i = 0; i < HID; i++) whh[j][i] = W_hh[j * HID + i];

        float ha = h0[b * HID + 0];
        float hb = h0[b * HID + 1];
        float hc = h0[b * HID + 2];

        float* __restrict__ outs  = out;
        float* __restrict__ hlast = out + (size_t)SEQ * BATCH * HID;

        uint32_t cph = 0;
        for (int g = 0; g < NGRP; g++) {
            const int slot = g & (RS - 1);
            mbar_wait(smem_u32(&mb_full[slot]), cph);   // acquire: p visible

            const int t0 = g * UNR;
#pragma unroll
            for (int k = 0; k < UNR; k++) {
                const float4 p = pr[slot][k][lane];

                float a0 = fmaf(whh[0][0], ha, p.x);
                float a1 = fmaf(whh[1][0], ha, p.y);
                float a2 = fmaf(whh[2][0], ha, p.z);
                a0 = fmaf(whh[0][1], hb, a0);
                a1 = fmaf(whh[1][1], hb, a1);
                a2 = fmaf(whh[2][1], hb, a2);
                a0 = fmaf(whh[0][2], hc, a0);
                a1 = fmaf(whh[1][2], hc, a1);
                a2 = fmaf(whh[2][2], hc, a2);

                ha = fmaxf(a0, 0.0f);
                hb = fmaxf(a1, 0.0f);
                hc = fmaxf(a2, 0.0f);

                const size_t o = ((size_t)(t0 + k) * BATCH + b) * HID;
                __stcs(outs + o + 0, ha);
                __stcs(outs + o + 1, hb);
                __stcs(outs + o + 2, hc);
            }
            mbar_arrive(smem_u32(&mb_empty[slot]));     // slot consumed

            if (slot == RS - 1) cph ^= 1;
        }

        hlast[b * HID + 0] = ha;
        hlast[b * HID + 1] = hb;
        hlast[b * HID + 2] = hc;
    }
}

extern "C" void kernel_launch(void* const* d_in, const int* in_sizes, int n_in,
                              void* d_out, int out_size)
{
    const float* x    = (const float*)d_in[0];
    const float* h0   = (const float*)d_in[1];
    const float* W_ih = (const float*)d_in[2];
    const float* W_hh = (const float*)d_in[3];
    const float* b_ih = (const float*)d_in[4];
    const float* b_hh = (const float*)d_in[5];
    float* out = (float*)d_out;

    // 128 blocks x 2 warps (consumer + producer), mbarrier-coupled ring.
    rnn_relu_kernel<<<BATCH / 32, 64>>>(x, h0, W_ih, W_hh, b_ih, b_hh, out);
}